// round 2
// baseline (speedup 1.0000x reference)
#include <cuda_runtime.h>
#include <math.h>

#define NN 20000
#define EE 160000
#define ET (EE + NN)
#define DIM 768
#define IND 2304
#define CLS 32
#define EPS_BN 1e-5f
#define SLOPE 0.2f

// ---------------- scratch (device globals; no allocation) ----------------
__device__ float g_xn[(size_t)NN * IND];   // 184 MB
__device__ float g_xl[(size_t)NN * DIM];   // 61 MB (reused: xl1 then xl2)
__device__ float g_h1[(size_t)NN * DIM];   // 61 MB
__device__ float g_al[NN];
__device__ float g_ar[NN];
__device__ float g_stats[2 * IND];
__device__ float g_scale[IND];
__device__ float g_shift[IND];
__device__ int   g_deg[NN];
__device__ int   g_off[NN + 1];
__device__ int   g_cur[NN];
__device__ int   g_srcs[ET];
__device__ float g_acc[8];

// ---------------- utility zero kernels ----------------
__global__ void zero_small_k() {
    int i = blockIdx.x * blockDim.x + threadIdx.x;
    if (i < 2 * IND) g_stats[i] = 0.f;
    if (i < 8) g_acc[i] = 0.f;
}
__global__ void zero_deg_k() {
    int i = blockIdx.x * blockDim.x + threadIdx.x;
    if (i < NN) g_deg[i] = 0;
}

// ---------------- BatchNorm ----------------
__global__ void bn_stats_k(const float* __restrict__ x) {
    int c = blockIdx.x * blockDim.x + threadIdx.x;
    if (c >= IND) return;
    int r0 = blockIdx.y * 128;
    int r1 = min(r0 + 128, NN);
    float s = 0.f, s2 = 0.f;
    for (int r = r0; r < r1; r++) {
        float v = x[(size_t)r * IND + c];
        s += v; s2 += v * v;
    }
    atomicAdd(&g_stats[c], s);
    atomicAdd(&g_stats[IND + c], s2);
}
__global__ void bn_finalize_k(const float* __restrict__ gamma, const float* __restrict__ beta) {
    int c = blockIdx.x * blockDim.x + threadIdx.x;
    if (c >= IND) return;
    float mu = g_stats[c] / (float)NN;
    float var = g_stats[IND + c] / (float)NN - mu * mu;
    float inv = 1.f / sqrtf(var + EPS_BN);
    float sc = gamma[c] * inv;
    g_scale[c] = sc;
    g_shift[c] = beta[c] - mu * sc;
}
__global__ void bn_apply_k(const float* __restrict__ x) {
    const size_t total4 = (size_t)NN * IND / 4;
    size_t stride = (size_t)gridDim.x * blockDim.x;
    for (size_t i = blockIdx.x * (size_t)blockDim.x + threadIdx.x; i < total4; i += stride) {
        int c = (int)(i % (IND / 4)) * 4;
        float4 v = ((const float4*)x)[i];
        float4 o;
        o.x = v.x * g_scale[c + 0] + g_shift[c + 0];
        o.y = v.y * g_scale[c + 1] + g_shift[c + 1];
        o.z = v.z * g_scale[c + 2] + g_shift[c + 2];
        o.w = v.w * g_scale[c + 3] + g_shift[c + 3];
        ((float4*)g_xn)[i] = o;
    }
}

// ---------------- SGEMM: C[M,N] = A[M,K] @ B[K,N] (+bias) (+=C if beta) ----------------
template<int BM, int BN, int BK, int TM, int TN>
__global__ void __launch_bounds__((BM / TM) * (BN / TN))
sgemm_k(const float* __restrict__ A, const float* __restrict__ B,
        const float* __restrict__ bias, float* __restrict__ C,
        int M, int N, int K, int beta) {
    constexpr int THREADS = (BM / TM) * (BN / TN);
    __shared__ float As[BK][BM + 1];
    __shared__ float Bs[BK][BN];
    int tid = threadIdx.x;
    int block_row = blockIdx.y * BM;
    int block_col = blockIdx.x * BN;
    int tr = tid / (BN / TN);
    int tc = tid % (BN / TN);
    float acc[TM][TN];
#pragma unroll
    for (int i = 0; i < TM; i++)
#pragma unroll
        for (int j = 0; j < TN; j++) acc[i][j] = 0.f;

    for (int k0 = 0; k0 < K; k0 += BK) {
#pragma unroll 4
        for (int i = tid; i < BM * BK; i += THREADS) {
            int r = i / BK, c = i % BK;
            int gr = block_row + r;
            As[c][r] = (gr < M) ? A[(size_t)gr * K + k0 + c] : 0.f;
        }
#pragma unroll 4
        for (int i = tid; i < BK * BN; i += THREADS) {
            int r = i / BN, c = i % BN;
            int gc = block_col + c;
            Bs[r][c] = (gc < N) ? B[(size_t)(k0 + r) * N + gc] : 0.f;
        }
        __syncthreads();
#pragma unroll
        for (int kk = 0; kk < BK; kk++) {
            float a[TM], b[TN];
#pragma unroll
            for (int i = 0; i < TM; i++) a[i] = As[kk][tr * TM + i];
#pragma unroll
            for (int j = 0; j < TN; j++) b[j] = Bs[kk][tc * TN + j];
#pragma unroll
            for (int i = 0; i < TM; i++)
#pragma unroll
                for (int j = 0; j < TN; j++) acc[i][j] += a[i] * b[j];
        }
        __syncthreads();
    }
#pragma unroll
    for (int i = 0; i < TM; i++) {
        int gr = block_row + tr * TM + i;
        if (gr >= M) continue;
#pragma unroll
        for (int j = 0; j < TN; j++) {
            int gc = block_col + tc * TN + j;
            if (gc >= N) continue;
            float v = acc[i][j];
            if (bias) v += bias[gc];
            if (beta) v += C[(size_t)gr * N + gc];
            C[(size_t)gr * N + gc] = v;
        }
    }
}

// ---------------- CSR build (by dst) ----------------
__global__ void count_k(const int* __restrict__ ei) {
    int j = blockIdx.x * blockDim.x + threadIdx.x;
    if (j >= ET) return;
    int dd = (j < EE) ? ei[EE + j] : (j - EE);
    atomicAdd(&g_deg[dd], 1);
}
__global__ void scan_k() {
    __shared__ int tsum[1024];
    int tid = threadIdx.x;
    const int CH = (NN + 1023) / 1024;  // 20
    int b = tid * CH;
    int loc = 0;
    for (int i = 0; i < CH; i++) {
        int idx = b + i;
        if (idx < NN) loc += g_deg[idx];
    }
    tsum[tid] = loc;
    __syncthreads();
    if (tid == 0) {
        int run = 0;
        for (int i = 0; i < 1024; i++) { int t = tsum[i]; tsum[i] = run; run += t; }
        g_off[NN] = run;
    }
    __syncthreads();
    int run = tsum[tid];
    for (int i = 0; i < CH; i++) {
        int idx = b + i;
        if (idx < NN) {
            g_off[idx] = run;
            g_cur[idx] = run;
            run += g_deg[idx];
        }
    }
}
__global__ void scatter_k(const int* __restrict__ ei) {
    int j = blockIdx.x * blockDim.x + threadIdx.x;
    if (j >= ET) return;
    int s, dd;
    if (j < EE) { s = ei[j]; dd = ei[EE + j]; }
    else        { s = j - EE; dd = j - EE; }
    int pos = atomicAdd(&g_cur[dd], 1);
    g_srcs[pos] = s;
}

// ---------------- attention scalars: al = xl@a_src, ar = xl@a_dst ----------------
__global__ void alar_k(const float* __restrict__ xl,
                       const float* __restrict__ asrc, const float* __restrict__ adst) {
    int gw = (blockIdx.x * blockDim.x + threadIdx.x) >> 5;
    int lane = threadIdx.x & 31;
    if (gw >= NN) return;
    const float* row = xl + (size_t)gw * DIM;
    float s1 = 0.f, s2 = 0.f;
    for (int c = lane; c < DIM; c += 32) {
        float v = row[c];
        s1 += v * asrc[c];
        s2 += v * adst[c];
    }
#pragma unroll
    for (int o = 16; o; o >>= 1) {
        s1 += __shfl_xor_sync(0xffffffffu, s1, o);
        s2 += __shfl_xor_sync(0xffffffffu, s2, o);
    }
    if (lane == 0) { g_al[gw] = s1; g_ar[gw] = s2; }
}

// ---------------- GAT aggregation (segment softmax + weighted sum + bias) ----------------
__global__ void __launch_bounds__(256)
gat_agg_k(const float* __restrict__ xl, const float* __restrict__ bias,
          float* __restrict__ out) {
    const int node = blockIdx.x;
    const int beg = g_off[node], end = g_off[node + 1];
    const float ar_i = g_ar[node];
    __shared__ float sh_m, sh_den;
    __shared__ float sh_coef[256];
    __shared__ int   sh_src[256];
    int tid = threadIdx.x;

    if (tid < 32) {
        float m = -INFINITY;
        for (int j = beg + tid; j < end; j += 32) {
            float e = g_al[g_srcs[j]] + ar_i;
            e = (e > 0.f) ? e : SLOPE * e;
            m = fmaxf(m, e);
        }
#pragma unroll
        for (int o = 16; o; o >>= 1) m = fmaxf(m, __shfl_xor_sync(0xffffffffu, m, o));
        float den = 0.f;
        for (int j = beg + tid; j < end; j += 32) {
            float e = g_al[g_srcs[j]] + ar_i;
            e = (e > 0.f) ? e : SLOPE * e;
            den += expf(e - m);
        }
#pragma unroll
        for (int o = 16; o; o >>= 1) den += __shfl_xor_sync(0xffffffffu, den, o);
        if (tid == 0) { sh_m = m; sh_den = den + 1e-16f; }
    }
    __syncthreads();
    const float m = sh_m;
    const float inv_den = 1.f / sh_den;

    float a0 = 0.f, a1 = 0.f, a2 = 0.f;
    const int c = tid;  // 256 threads, 3 columns each (DIM=768)
    for (int cb = beg; cb < end; cb += 256) {
        int cnt = min(256, end - cb);
        if (tid < cnt) {
            int s = g_srcs[cb + tid];
            float e = g_al[s] + ar_i;
            e = (e > 0.f) ? e : SLOPE * e;
            sh_src[tid] = s;
            sh_coef[tid] = expf(e - m) * inv_den;
        }
        __syncthreads();
        for (int jj = 0; jj < cnt; jj++) {
            const float* row = xl + (size_t)sh_src[jj] * DIM;
            float w = sh_coef[jj];
            a0 += w * row[c];
            a1 += w * row[c + 256];
            a2 += w * row[c + 512];
        }
        __syncthreads();
    }
    float* orow = out + (size_t)node * DIM;
    orow[c]       = a0 + bias[c];
    orow[c + 256] = a1 + bias[c + 256];
    orow[c + 512] = a2 + bias[c + 512];
}

// ---------------- masked CE + accuracy (warp per node, lane = class) ----------------
__global__ void ce_k(const float* __restrict__ logits, const int* __restrict__ target,
                     int accbase) {
    int gw = (blockIdx.x * blockDim.x + threadIdx.x) >> 5;
    int lane = threadIdx.x & 31;
    if (gw >= NN) return;
    float v = logits[(size_t)gw * CLS + lane];
    float mx = v;
#pragma unroll
    for (int o = 16; o; o >>= 1) mx = fmaxf(mx, __shfl_xor_sync(0xffffffffu, mx, o));
    float ex = expf(v - mx);
    float sum = ex;
#pragma unroll
    for (int o = 16; o; o >>= 1) sum += __shfl_xor_sync(0xffffffffu, sum, o);
    int t = target[gw];
    if (t < 0) return;
    unsigned mask = __ballot_sync(0xffffffffu, v == mx);
    int amax = __ffs(mask) - 1;  // first max index == jnp.argmax tie-break
    if (lane == t) {
        float nll = -(v - mx - logf(sum));
        atomicAdd(&g_acc[accbase + 0], nll);
    }
    if (lane == 0) {
        atomicAdd(&g_acc[accbase + 1], (amax == t) ? 1.f : 0.f);
        atomicAdd(&g_acc[accbase + 2], 1.f);
    }
}
__global__ void final_k(float* __restrict__ out_scal) {
    out_scal[0] = g_acc[0] / g_acc[2] + g_acc[3] / g_acc[5];  // loss
    out_scal[1] = g_acc[1] / g_acc[2];                        // acc_gcn
    out_scal[2] = g_acc[4] / g_acc[5];                        // acc_lin
}

// ---------------- driver ----------------
extern "C" void kernel_launch(void* const* d_in, const int* in_sizes, int n_in,
                              void* d_out, int out_size) {
    const float* x     = (const float*)d_in[0];
    const int*   ei    = (const int*)d_in[1];
    const int*   target= (const int*)d_in[2];
    const float* gamma = (const float*)d_in[3];
    const float* beta  = (const float*)d_in[4];
    const float* W1    = (const float*)d_in[5];
    const float* as1   = (const float*)d_in[6];
    const float* ad1   = (const float*)d_in[7];
    const float* b1    = (const float*)d_in[8];
    const float* W2    = (const float*)d_in[9];
    const float* as2   = (const float*)d_in[10];
    const float* ad2   = (const float*)d_in[11];
    const float* b2    = (const float*)d_in[12];
    const float* poolW = (const float*)d_in[13];
    const float* poolb = (const float*)d_in[14];
    const float* dirW  = (const float*)d_in[15];
    const float* dirb  = (const float*)d_in[16];
    float* out = (float*)d_out;

    const size_t OFF_DIR  = (size_t)NN * DIM;
    const size_t OFF_POOL = OFF_DIR + (size_t)NN * CLS;
    const size_t OFF_SCAL = OFF_POOL + (size_t)NN * CLS;

    float *p_xn, *p_xl, *p_h1;
    cudaGetSymbolAddress((void**)&p_xn, g_xn);
    cudaGetSymbolAddress((void**)&p_xl, g_xl);
    cudaGetSymbolAddress((void**)&p_h1, g_h1);

    // zero accumulators
    zero_small_k<<<(2 * IND + 255) / 256, 256>>>();
    zero_deg_k<<<(NN + 255) / 256, 256>>>();

    // BatchNorm
    bn_stats_k<<<dim3((IND + 255) / 256, (NN + 127) / 128), 256>>>(x);
    bn_finalize_k<<<(IND + 255) / 256, 256>>>(gamma, beta);
    bn_apply_k<<<4096, 256>>>(x);

    // direct head: xn @ dir_W + dir_b
    sgemm_k<128, 32, 32, 8, 2><<<dim3(1, (NN + 127) / 128), 256>>>(
        p_xn, dirW, dirb, out + OFF_DIR, NN, CLS, IND, 0);

    // CSR by dst
    count_k<<<(ET + 255) / 256, 256>>>(ei);
    scan_k<<<1, 1024>>>();
    scatter_k<<<(ET + 255) / 256, 256>>>(ei);

    // ---- GAT layer 1 ----
    sgemm_k<128, 64, 16, 8, 4><<<dim3(DIM / 64, (NN + 127) / 128), 256>>>(
        p_xn, W1, nullptr, p_xl, NN, DIM, IND, 0);
    alar_k<<<(NN * 32 + 255) / 256, 256>>>(p_xl, as1, ad1);
    gat_agg_k<<<NN, 256>>>(p_xl, b1, p_h1);

    // ---- GAT layer 2: xl2 = h1 @ W2[0:768] + xn @ W2[768:3072] ----
    sgemm_k<128, 64, 16, 8, 4><<<dim3(DIM / 64, (NN + 127) / 128), 256>>>(
        p_h1, W2, nullptr, p_xl, NN, DIM, DIM, 0);
    sgemm_k<128, 64, 16, 8, 4><<<dim3(DIM / 64, (NN + 127) / 128), 256>>>(
        p_xn, W2 + (size_t)DIM * DIM, nullptr, p_xl, NN, DIM, IND, 1);
    alar_k<<<(NN * 32 + 255) / 256, 256>>>(p_xl, as2, ad2);
    gat_agg_k<<<NN, 256>>>(p_xl, b2, out /* h2 */);

    // pooler: h2 @ pool_W + pool_b
    sgemm_k<128, 32, 32, 8, 2><<<dim3(1, (NN + 127) / 128), 256>>>(
        out, poolW, poolb, out + OFF_POOL, NN, CLS, DIM, 0);

    // losses + accuracies
    ce_k<<<(NN * 32 + 255) / 256, 256>>>(out + OFF_POOL, target, 0);
    ce_k<<<(NN * 32 + 255) / 256, 256>>>(out + OFF_DIR, target, 3);
    final_k<<<1, 1>>>(out + OFF_SCAL);
}

// round 4
// speedup vs baseline: 1.4878x; 1.4878x over previous
#include <cuda_runtime.h>
#include <math.h>
#include <stdint.h>

#define NN 20000
#define EE 160000
#define ET (EE + NN)
#define DIM 768
#define IND 2304
#define CLS 32
#define EPS_BN 1e-5f
#define SLOPE 0.2f

// ---------------- scratch (device globals; no allocation) ----------------
__device__ float g_xn[(size_t)NN * IND];
__device__ float g_xl[(size_t)NN * DIM];
__device__ float g_h1[(size_t)NN * DIM];
__device__ float g_al[NN];
__device__ float g_ar[NN];
__device__ float g_stats[2 * IND];
__device__ float g_scale[IND];
__device__ float g_shift[IND];
__device__ int   g_deg[NN];
__device__ int   g_off[NN + 1];
__device__ int   g_cur[NN];
__device__ int   g_srcs[ET];
__device__ float g_acc[8];

// ---------------- utility zero kernels ----------------
__global__ void zero_small_k() {
    int i = blockIdx.x * blockDim.x + threadIdx.x;
    if (i < 2 * IND) g_stats[i] = 0.f;
    if (i < 8) g_acc[i] = 0.f;
}
__global__ void zero_deg_k() {
    int i = blockIdx.x * blockDim.x + threadIdx.x;
    if (i < NN) g_deg[i] = 0;
}

// ---------------- BatchNorm ----------------
__global__ void bn_stats_k(const float* __restrict__ x) {
    int c = blockIdx.x * blockDim.x + threadIdx.x;
    if (c >= IND) return;
    int r0 = blockIdx.y * 128;
    int r1 = min(r0 + 128, NN);
    float s = 0.f, s2 = 0.f;
    for (int r = r0; r < r1; r++) {
        float v = x[(size_t)r * IND + c];
        s += v; s2 += v * v;
    }
    atomicAdd(&g_stats[c], s);
    atomicAdd(&g_stats[IND + c], s2);
}
__global__ void bn_finalize_k(const float* __restrict__ gamma, const float* __restrict__ beta) {
    int c = blockIdx.x * blockDim.x + threadIdx.x;
    if (c >= IND) return;
    float mu = g_stats[c] / (float)NN;
    float var = g_stats[IND + c] / (float)NN - mu * mu;
    float inv = 1.f / sqrtf(var + EPS_BN);
    float sc = gamma[c] * inv;
    g_scale[c] = sc;
    g_shift[c] = beta[c] - mu * sc;
}
__global__ void bn_apply_k(const float* __restrict__ x) {
    const size_t total4 = (size_t)NN * IND / 4;
    size_t stride = (size_t)gridDim.x * blockDim.x;
    for (size_t i = blockIdx.x * (size_t)blockDim.x + threadIdx.x; i < total4; i += stride) {
        int c = (int)(i % (IND / 4)) * 4;
        float4 v = ((const float4*)x)[i];
        float4 o;
        o.x = v.x * g_scale[c + 0] + g_shift[c + 0];
        o.y = v.y * g_scale[c + 1] + g_shift[c + 1];
        o.z = v.z * g_scale[c + 2] + g_shift[c + 2];
        o.w = v.w * g_scale[c + 3] + g_shift[c + 3];
        ((float4*)g_xn)[i] = o;
    }
}

// ---------------- tf32 helpers ----------------
__device__ __forceinline__ uint32_t f2tf(float f) {
    uint32_t u;
    asm("cvt.rna.tf32.f32 %0, %1;" : "=r"(u) : "f"(f));
    return u;
}
__device__ __forceinline__ void mma_tf32(float* d, const uint32_t* a, const uint32_t* b) {
    asm volatile(
        "mma.sync.aligned.m16n8k8.row.col.f32.tf32.tf32.f32 "
        "{%0,%1,%2,%3},{%4,%5,%6,%7},{%8,%9},{%0,%1,%2,%3};"
        : "+f"(d[0]), "+f"(d[1]), "+f"(d[2]), "+f"(d[3])
        : "r"(a[0]), "r"(a[1]), "r"(a[2]), "r"(a[3]), "r"(b[0]), "r"(b[1]));
}

// ---------------- 3xTF32 GEMM: C[M,N] = [A1;A2][M, K1+K2] @ B[K1+K2, N] ----------------
// BM=128, BN=128, BK=16. 128 threads = 4 warps (2x2), warp tile 64x64.
// Full-fp32-accuracy via hi/lo split (a_lo*b_hi + a_hi*b_lo + a_hi*b_hi).
#define AST 20  // As row stride (20 mod 32 spreads 8 rows over all banks)
__global__ void __launch_bounds__(128)
tf32gemm3x_k(const float* __restrict__ A1, int K1,
             const float* __restrict__ A2, int K2,
             const float* __restrict__ B, float* __restrict__ C,
             int M, int N) {
    __shared__ uint32_t AsH[128 * AST];
    __shared__ uint32_t AsL[128 * AST];
    __shared__ uint32_t BsH[16 * 128];
    __shared__ uint32_t BsL[16 * 128];
    const int tid = threadIdx.x;
    const int wid = tid >> 5, lane = tid & 31;
    const int bm0 = blockIdx.y * 128, bn0 = blockIdx.x * 128;
    const int wm0 = (wid >> 1) * 64;   // 0 or 64
    const int wn0 = (wid & 1) * 64;    // 0 or 64
    const int r0 = lane >> 2, c0 = lane & 3;
    const int bsw = c0 * 8;            // B swizzle factor for fragment loads

    float acc[4][8][4];
#pragma unroll
    for (int i = 0; i < 4; i++)
#pragma unroll
        for (int j = 0; j < 8; j++)
#pragma unroll
            for (int v = 0; v < 4; v++) acc[i][j][v] = 0.f;

    const int KT = (K1 + K2) / 16;
    for (int kt = 0; kt < KT; kt++) {
        const int k0 = kt * 16;
        const float* Ap; int lda, ka;
        if (k0 < K1) { Ap = A1; lda = K1; ka = k0; }
        else         { Ap = A2; lda = K2; ka = k0 - K1; }

        // A tile: 128 x 16 floats -> hi/lo tf32
#pragma unroll
        for (int it = 0; it < 4; it++) {
            int idx = it * 128 + tid;
            int m = idx >> 2, kc = (idx & 3) * 4;
            float4 v = make_float4(0.f, 0.f, 0.f, 0.f);
            int gr = bm0 + m;
            if (gr < M) v = *(const float4*)(Ap + (size_t)gr * lda + ka + kc);
            uint4 h, l;
            h.x = f2tf(v.x); l.x = f2tf(v.x - __uint_as_float(h.x));
            h.y = f2tf(v.y); l.y = f2tf(v.y - __uint_as_float(h.y));
            h.z = f2tf(v.z); l.z = f2tf(v.z - __uint_as_float(h.z));
            h.w = f2tf(v.w); l.w = f2tf(v.w - __uint_as_float(h.w));
            *(uint4*)(&AsH[m * AST + kc]) = h;
            *(uint4*)(&AsL[m * AST + kc]) = l;
        }
        // B tile: 16 x 128, k-major, XOR-swizzled columns (blocks of 8 floats)
#pragma unroll
        for (int it = 0; it < 4; it++) {
            int idx = it * 128 + tid;
            int kk = idx >> 5, n4 = (idx & 31) * 4;
            int col = n4 ^ ((kk & 3) * 8);
            float4 v = *(const float4*)(B + (size_t)(k0 + kk) * N + bn0 + n4);
            uint4 h, l;
            h.x = f2tf(v.x); l.x = f2tf(v.x - __uint_as_float(h.x));
            h.y = f2tf(v.y); l.y = f2tf(v.y - __uint_as_float(h.y));
            h.z = f2tf(v.z); l.z = f2tf(v.z - __uint_as_float(h.z));
            h.w = f2tf(v.w); l.w = f2tf(v.w - __uint_as_float(h.w));
            *(uint4*)(&BsH[kk * 128 + col]) = h;
            *(uint4*)(&BsL[kk * 128 + col]) = l;
        }
        __syncthreads();

#pragma unroll
        for (int sub = 0; sub < 2; sub++) {
            const int kb = sub * 8;
            uint32_t ah[4][4], al_[4][4];
#pragma unroll
            for (int mt = 0; mt < 4; mt++) {
                int ra = (wm0 + mt * 16 + r0) * AST + kb + c0;
                int rb = ra + 8 * AST;
                ah[mt][0] = AsH[ra];     al_[mt][0] = AsL[ra];
                ah[mt][1] = AsH[rb];     al_[mt][1] = AsL[rb];
                ah[mt][2] = AsH[ra + 4]; al_[mt][2] = AsL[ra + 4];
                ah[mt][3] = AsH[rb + 4]; al_[mt][3] = AsL[rb + 4];
            }
#pragma unroll
            for (int half = 0; half < 2; half++) {
                uint32_t bh[4][2], bl[4][2];
#pragma unroll
                for (int q = 0; q < 4; q++) {
                    int nt = half * 4 + q;
                    int nb = (wn0 + nt * 8 + r0) ^ bsw;
                    int i0 = (kb + c0) * 128 + nb;
                    int i1 = i0 + 4 * 128;
                    bh[q][0] = BsH[i0]; bl[q][0] = BsL[i0];
                    bh[q][1] = BsH[i1]; bl[q][1] = BsL[i1];
                }
#pragma unroll
                for (int mt = 0; mt < 4; mt++)
#pragma unroll
                    for (int q = 0; q < 4; q++) {
                        float* a = acc[mt][half * 4 + q];
                        mma_tf32(a, al_[mt], bh[q]);   // a_lo * b_hi
                        mma_tf32(a, ah[mt], bl[q]);    // a_hi * b_lo
                        mma_tf32(a, ah[mt], bh[q]);    // a_hi * b_hi
                    }
            }
        }
        __syncthreads();
    }

    // epilogue
#pragma unroll
    for (int mt = 0; mt < 4; mt++) {
        int gr0 = bm0 + wm0 + mt * 16 + r0;
        int gr1 = gr0 + 8;
#pragma unroll
        for (int nt = 0; nt < 8; nt++) {
            int gc = bn0 + wn0 + nt * 8 + 2 * c0;
            if (gr0 < M)
                *(float2*)(C + (size_t)gr0 * N + gc) = make_float2(acc[mt][nt][0], acc[mt][nt][1]);
            if (gr1 < M)
                *(float2*)(C + (size_t)gr1 * N + gc) = make_float2(acc[mt][nt][2], acc[mt][nt][3]);
        }
    }
}

// ---------------- SIMT SGEMM (small-N heads): C = A@B (+bias) ----------------
template<int BM, int BN, int BK, int TM, int TN>
__global__ void __launch_bounds__((BM / TM) * (BN / TN))
sgemm_k(const float* __restrict__ A, const float* __restrict__ B,
        const float* __restrict__ bias, float* __restrict__ C,
        int M, int N, int K) {
    constexpr int THREADS = (BM / TM) * (BN / TN);
    __shared__ float As[BK][BM + 1];
    __shared__ float Bs[BK][BN];
    int tid = threadIdx.x;
    int block_row = blockIdx.y * BM;
    int block_col = blockIdx.x * BN;
    int tr = tid / (BN / TN);
    int tc = tid % (BN / TN);
    float acc[TM][TN];
#pragma unroll
    for (int i = 0; i < TM; i++)
#pragma unroll
        for (int j = 0; j < TN; j++) acc[i][j] = 0.f;

    for (int k0 = 0; k0 < K; k0 += BK) {
#pragma unroll 4
        for (int i = tid; i < BM * BK; i += THREADS) {
            int r = i / BK, c = i % BK;
            int gr = block_row + r;
            As[c][r] = (gr < M) ? A[(size_t)gr * K + k0 + c] : 0.f;
        }
#pragma unroll 4
        for (int i = tid; i < BK * BN; i += THREADS) {
            int r = i / BN, c = i % BN;
            int gc = block_col + c;
            Bs[r][c] = (gc < N) ? B[(size_t)(k0 + r) * N + gc] : 0.f;
        }
        __syncthreads();
#pragma unroll
        for (int kk = 0; kk < BK; kk++) {
            float a[TM], b[TN];
#pragma unroll
            for (int i = 0; i < TM; i++) a[i] = As[kk][tr * TM + i];
#pragma unroll
            for (int j = 0; j < TN; j++) b[j] = Bs[kk][tc * TN + j];
#pragma unroll
            for (int i = 0; i < TM; i++)
#pragma unroll
                for (int j = 0; j < TN; j++) acc[i][j] += a[i] * b[j];
        }
        __syncthreads();
    }
#pragma unroll
    for (int i = 0; i < TM; i++) {
        int gr = block_row + tr * TM + i;
        if (gr >= M) continue;
#pragma unroll
        for (int j = 0; j < TN; j++) {
            int gc = block_col + tc * TN + j;
            if (gc >= N) continue;
            float v = acc[i][j];
            if (bias) v += bias[gc];
            C[(size_t)gr * N + gc] = v;
        }
    }
}

// ---------------- CSR build (by dst) ----------------
__global__ void count_k(const int* __restrict__ ei) {
    int j = blockIdx.x * blockDim.x + threadIdx.x;
    if (j >= ET) return;
    int dd = (j < EE) ? ei[EE + j] : (j - EE);
    atomicAdd(&g_deg[dd], 1);
}
__global__ void scan_k() {
    __shared__ int tsum[1024];
    int tid = threadIdx.x;
    const int CH = (NN + 1023) / 1024;
    int b = tid * CH;
    int loc = 0;
    for (int i = 0; i < CH; i++) {
        int idx = b + i;
        if (idx < NN) loc += g_deg[idx];
    }
    tsum[tid] = loc;
    __syncthreads();
    if (tid == 0) {
        int run = 0;
        for (int i = 0; i < 1024; i++) { int t = tsum[i]; tsum[i] = run; run += t; }
        g_off[NN] = run;
    }
    __syncthreads();
    int run = tsum[tid];
    for (int i = 0; i < CH; i++) {
        int idx = b + i;
        if (idx < NN) {
            g_off[idx] = run;
            g_cur[idx] = run;
            run += g_deg[idx];
        }
    }
}
__global__ void scatter_k(const int* __restrict__ ei) {
    int j = blockIdx.x * blockDim.x + threadIdx.x;
    if (j >= ET) return;
    int s, dd;
    if (j < EE) { s = ei[j]; dd = ei[EE + j]; }
    else        { s = j - EE; dd = j - EE; }
    int pos = atomicAdd(&g_cur[dd], 1);
    g_srcs[pos] = s;
}

// ---------------- attention scalars ----------------
__global__ void alar_k(const float* __restrict__ xl,
                       const float* __restrict__ asrc, const float* __restrict__ adst) {
    int gw = (blockIdx.x * blockDim.x + threadIdx.x) >> 5;
    int lane = threadIdx.x & 31;
    if (gw >= NN) return;
    const float* row = xl + (size_t)gw * DIM;
    float s1 = 0.f, s2 = 0.f;
    for (int c = lane; c < DIM; c += 32) {
        float v = row[c];
        s1 += v * asrc[c];
        s2 += v * adst[c];
    }
#pragma unroll
    for (int o = 16; o; o >>= 1) {
        s1 += __shfl_xor_sync(0xffffffffu, s1, o);
        s2 += __shfl_xor_sync(0xffffffffu, s2, o);
    }
    if (lane == 0) { g_al[gw] = s1; g_ar[gw] = s2; }
}

// ---------------- GAT aggregation ----------------
__global__ void __launch_bounds__(256)
gat_agg_k(const float* __restrict__ xl, const float* __restrict__ bias,
          float* __restrict__ out) {
    const int node = blockIdx.x;
    const int beg = g_off[node], end = g_off[node + 1];
    const float ar_i = g_ar[node];
    __shared__ float sh_m, sh_den;
    __shared__ float sh_coef[256];
    __shared__ int   sh_src[256];
    int tid = threadIdx.x;

    if (tid < 32) {
        float m = -INFINITY;
        for (int j = beg + tid; j < end; j += 32) {
            float e = g_al[g_srcs[j]] + ar_i;
            e = (e > 0.f) ? e : SLOPE * e;
            m = fmaxf(m, e);
        }
#pragma unroll
        for (int o = 16; o; o >>= 1) m = fmaxf(m, __shfl_xor_sync(0xffffffffu, m, o));
        float den = 0.f;
        for (int j = beg + tid; j < end; j += 32) {
            float e = g_al[g_srcs[j]] + ar_i;
            e = (e > 0.f) ? e : SLOPE * e;
            den += expf(e - m);
        }
#pragma unroll
        for (int o = 16; o; o >>= 1) den += __shfl_xor_sync(0xffffffffu, den, o);
        if (tid == 0) { sh_m = m; sh_den = den + 1e-16f; }
    }
    __syncthreads();
    const float m = sh_m;
    const float inv_den = 1.f / sh_den;

    float a0 = 0.f, a1 = 0.f, a2 = 0.f;
    const int c = tid;
    for (int cb = beg; cb < end; cb += 256) {
        int cnt = min(256, end - cb);
        if (tid < cnt) {
            int s = g_srcs[cb + tid];
            float e = g_al[s] + ar_i;
            e = (e > 0.f) ? e : SLOPE * e;
            sh_src[tid] = s;
            sh_coef[tid] = expf(e - m) * inv_den;
        }
        __syncthreads();
        for (int jj = 0; jj < cnt; jj++) {
            const float* row = xl + (size_t)sh_src[jj] * DIM;
            float w = sh_coef[jj];
            a0 += w * row[c];
            a1 += w * row[c + 256];
            a2 += w * row[c + 512];
        }
        __syncthreads();
    }
    float* orow = out + (size_t)node * DIM;
    orow[c]       = a0 + bias[c];
    orow[c + 256] = a1 + bias[c + 256];
    orow[c + 512] = a2 + bias[c + 512];
}

// ---------------- masked CE + accuracy ----------------
__global__ void ce_k(const float* __restrict__ logits, const int* __restrict__ target,
                     int accbase) {
    int gw = (blockIdx.x * blockDim.x + threadIdx.x) >> 5;
    int lane = threadIdx.x & 31;
    if (gw >= NN) return;
    float v = logits[(size_t)gw * CLS + lane];
    float mx = v;
#pragma unroll
    for (int o = 16; o; o >>= 1) mx = fmaxf(mx, __shfl_xor_sync(0xffffffffu, mx, o));
    float ex = expf(v - mx);
    float sum = ex;
#pragma unroll
    for (int o = 16; o; o >>= 1) sum += __shfl_xor_sync(0xffffffffu, sum, o);
    int t = target[gw];
    if (t < 0) return;
    unsigned mask = __ballot_sync(0xffffffffu, v == mx);
    int amax = __ffs(mask) - 1;
    if (lane == t) {
        float nll = -(v - mx - logf(sum));
        atomicAdd(&g_acc[accbase + 0], nll);
    }
    if (lane == 0) {
        atomicAdd(&g_acc[accbase + 1], (amax == t) ? 1.f : 0.f);
        atomicAdd(&g_acc[accbase + 2], 1.f);
    }
}
__global__ void final_k(float* __restrict__ out_scal) {
    out_scal[0] = g_acc[0] / g_acc[2] + g_acc[3] / g_acc[5];
    out_scal[1] = g_acc[1] / g_acc[2];
    out_scal[2] = g_acc[4] / g_acc[5];
}

// ---------------- driver ----------------
extern "C" void kernel_launch(void* const* d_in, const int* in_sizes, int n_in,
                              void* d_out, int out_size) {
    const float* x     = (const float*)d_in[0];
    const int*   ei    = (const int*)d_in[1];
    const int*   target= (const int*)d_in[2];
    const float* gamma = (const float*)d_in[3];
    const float* beta  = (const float*)d_in[4];
    const float* W1    = (const float*)d_in[5];
    const float* as1   = (const float*)d_in[6];
    const float* ad1   = (const float*)d_in[7];
    const float* b1    = (const float*)d_in[8];
    const float* W2    = (const float*)d_in[9];
    const float* as2   = (const float*)d_in[10];
    const float* ad2   = (const float*)d_in[11];
    const float* b2    = (const float*)d_in[12];
    const float* poolW = (const float*)d_in[13];
    const float* poolb = (const float*)d_in[14];
    const float* dirW  = (const float*)d_in[15];
    const float* dirb  = (const float*)d_in[16];
    float* out = (float*)d_out;

    const size_t OFF_DIR  = (size_t)NN * DIM;
    const size_t OFF_POOL = OFF_DIR + (size_t)NN * CLS;
    const size_t OFF_SCAL = OFF_POOL + (size_t)NN * CLS;

    float *p_xn, *p_xl, *p_h1;
    cudaGetSymbolAddress((void**)&p_xn, g_xn);
    cudaGetSymbolAddress((void**)&p_xl, g_xl);
    cudaGetSymbolAddress((void**)&p_h1, g_h1);

    zero_small_k<<<(2 * IND + 255) / 256, 256>>>();
    zero_deg_k<<<(NN + 255) / 256, 256>>>();

    // BatchNorm
    bn_stats_k<<<dim3((IND + 255) / 256, (NN + 127) / 128), 256>>>(x);
    bn_finalize_k<<<(IND + 255) / 256, 256>>>(gamma, beta);
    bn_apply_k<<<4096, 256>>>(x);

    // direct head: xn @ dir_W + dir_b (fp32 SIMT)
    sgemm_k<128, 32, 32, 8, 2><<<dim3(1, (NN + 127) / 128), 256>>>(
        p_xn, dirW, dirb, out + OFF_DIR, NN, CLS, IND);

    // CSR by dst
    count_k<<<(ET + 255) / 256, 256>>>(ei);
    scan_k<<<1, 1024>>>();
    scatter_k<<<(ET + 255) / 256, 256>>>(ei);

    // ---- GAT layer 1: xl1 = xn @ W1 (3xTF32 tensor cores, fp32 accuracy) ----
    tf32gemm3x_k<<<dim3(DIM / 128, (NN + 127) / 128), 128>>>(
        p_xn, IND, (const float*)nullptr, 0, W1, p_xl, NN, DIM);
    alar_k<<<(NN * 32 + 255) / 256, 256>>>(p_xl, as1, ad1);
    gat_agg_k<<<NN, 256>>>(p_xl, b1, p_h1);

    // ---- GAT layer 2 (fused K): xl2 = h1 @ W2[0:768] + xn @ W2[768:3072] ----
    tf32gemm3x_k<<<dim3(DIM / 128, (NN + 127) / 128), 128>>>(
        p_h1, DIM, p_xn, IND, W2, p_xl, NN, DIM);
    alar_k<<<(NN * 32 + 255) / 256, 256>>>(p_xl, as2, ad2);
    gat_agg_k<<<NN, 256>>>(p_xl, b2, out /* h2 */);

    // pooler: h2 @ pool_W + pool_b
    sgemm_k<128, 32, 32, 8, 2><<<dim3(1, (NN + 127) / 128), 256>>>(
        out, poolW, poolb, out + OFF_POOL, NN, CLS, DIM);

    // losses + accuracies
    ce_k<<<(NN * 32 + 255) / 256, 256>>>(out + OFF_POOL, target, 0);
    ce_k<<<(NN * 32 + 255) / 256, 256>>>(out + OFF_DIR, target, 3);
    final_k<<<1, 1>>>(out + OFF_SCAL);
}